// round 16
// baseline (speedup 1.0000x reference)
#include <cuda_runtime.h>
#include <cuda_bf16.h>
#include <cuda_fp16.h>
#include <cstdint>

// Problem constants (fixed by the dataset)
#define NN_MAX   50000
#define EDGE_MAX 800000
#define IN_CH    256
#define C1       128
#define C2       64

// -------- scratch (no allocations allowed -> __device__ globals) -----------
__device__ int    g_deg     [NN_MAX];
__device__ int    g_prefix  [NN_MAX];
__device__ int    g_bsum    [256];
__device__ int    g_rowstart[NN_MAX];
__device__ int    g_cursor  [NN_MAX];
__device__ int2   g_csr2    [EDGE_MAX];      // (src, dis[src] bits) grouped by dst
__device__ float  g_dis     [NN_MAX];
__device__ __half g_h1      [NN_MAX * C1];   // x@W1 (raw, fp16)
__device__ __half g_h2      [NN_MAX * C2];   // x2@W2 (raw, fp16)
// x2 (= relu layer-1 out) stored as PRE-SWIZZLED bf16 hi/lo planes:
// layout [chunk(2)][node][128B row, SW128-swizzled inner offset]
__device__ unsigned char g_x2hi[2 * NN_MAX * 128];
__device__ unsigned char g_x2lo[2 * NN_MAX * 128];
// Pre-swizzled (SW128) bf16 hi/lo images of W^T, layout [kchunk][n][k64], 128B rows.
__device__ uint4 g_W1hi[4096], g_W1lo[4096];   // 4 chunks x 128n x 128B
__device__ uint4 g_W2hi[1024], g_W2lo[1024];   // 2 chunks x  64n x 128B

#define SW128(o) ((o) ^ (((o) >> 3) & 0x70))

__device__ __forceinline__ uint32_t smem_u32(const void* p) {
    uint32_t a;
    asm("{ .reg .u64 t; cvta.to.shared.u64 t, %1; cvt.u32.u64 %0, t; }" : "=r"(a) : "l"(p));
    return a;
}
__device__ __forceinline__ void ldsm_x4(uint32_t* r, uint32_t addr) {
    asm volatile("ldmatrix.sync.aligned.m8n8.x4.shared.b16 {%0,%1,%2,%3}, [%4];"
                 : "=r"(r[0]), "=r"(r[1]), "=r"(r[2]), "=r"(r[3]) : "r"(addr));
}
__device__ __forceinline__ void mma_bf16(float* d, const uint32_t* a,
                                         uint32_t b0, uint32_t b1) {
    asm volatile(
        "mma.sync.aligned.m16n8k16.row.col.f32.bf16.bf16.f32 "
        "{%0,%1,%2,%3}, {%4,%5,%6,%7}, {%8,%9}, {%0,%1,%2,%3};"
        : "+f"(d[0]), "+f"(d[1]), "+f"(d[2]), "+f"(d[3])
        : "r"(a[0]), "r"(a[1]), "r"(a[2]), "r"(a[3]), "r"(b0), "r"(b1));
}
__device__ __forceinline__ void cp_async16(uint32_t saddr, const void* gaddr, int src_size) {
    asm volatile("cp.async.cg.shared.global [%0], [%1], 16, %2;"
                 :: "r"(saddr), "l"(gaddr), "r"(src_size) : "memory");
}
#define CP_COMMIT() asm volatile("cp.async.commit_group;" ::: "memory")
#define CP_WAIT0()  asm volatile("cp.async.wait_group 0;" ::: "memory")
#define CP_WAIT1()  asm volatile("cp.async.wait_group 1;" ::: "memory")

__device__ __forceinline__ uint32_t pack_bf2(__nv_bfloat16 a, __nv_bfloat16 b) {
    return ((uint32_t)__bfloat16_as_ushort(b) << 16) | __bfloat16_as_ushort(a);
}

// ---------------------------------------------------------------------------
// Fused prep: zero g_deg + build swizzled bf16 hi/lo weight images. (R9-proven)
__global__ void prep_kernel(const float* __restrict__ W1, const float* __restrict__ W2, int n) {
    int idx = blockIdx.x * blockDim.x + threadIdx.x;
    if (idx < n) g_deg[idx] = 0;
    if (idx < IN_CH * C1) {
        int k = idx / C1, nn = idx % C1;
        float v = W1[k * C1 + nn];
        __nv_bfloat16 h = __float2bfloat16_rn(v);
        __nv_bfloat16 l = __float2bfloat16_rn(v - __bfloat162float(h));
        int c = k >> 6, kk = k & 63;
        int off = c * 16384 + SW128(nn * 128 + kk * 2);
        *(__nv_bfloat16*)((char*)g_W1hi + off) = h;
        *(__nv_bfloat16*)((char*)g_W1lo + off) = l;
        if (idx < C1 * C2) {
            int k2 = idx / C2, n2 = idx % C2;
            float v2 = W2[k2 * C2 + n2];
            __nv_bfloat16 h2 = __float2bfloat16_rn(v2);
            __nv_bfloat16 l2 = __float2bfloat16_rn(v2 - __bfloat162float(h2));
            int c2 = k2 >> 6, kk2 = k2 & 63;
            int off2 = c2 * 8192 + SW128(n2 * 128 + kk2 * 2);
            *(__nv_bfloat16*)((char*)g_W2hi + off2) = h2;
            *(__nv_bfloat16*)((char*)g_W2lo + off2) = l2;
        }
    }
}

// Degree count: 4 edges per thread (int4 load) for MLP.
__global__ void deg_kernel(const int* __restrict__ dst, int E) {
    int base = (blockIdx.x * blockDim.x + threadIdx.x) * 4;
    if (base + 3 < E) {
        int4 d = *(const int4*)&dst[base];
        atomicAdd(&g_deg[d.x], 1);
        atomicAdd(&g_deg[d.y], 1);
        atomicAdd(&g_deg[d.z], 1);
        atomicAdd(&g_deg[d.w], 1);
    } else {
        for (int e = base; e < E; e++) atomicAdd(&g_deg[dst[e]], 1);
    }
}

// Parallel scan phase A: per-block exclusive prefix + block sums.
__global__ __launch_bounds__(512) void scanA(int n) {
    __shared__ int s[512];
    int t = threadIdx.x;
    int i = blockIdx.x * 512 + t;
    int v = (i < n) ? g_deg[i] : 0;
    s[t] = v; __syncthreads();
    for (int off = 1; off < 512; off <<= 1) {
        int u = (t >= off) ? s[t - off] : 0;
        __syncthreads(); s[t] += u; __syncthreads();
    }
    if (i < n) g_prefix[i] = s[t] - v;
    if (t == 511) g_bsum[blockIdx.x] = s[511];
}
// Phase B+C fused: every block redundantly scans the <=256 block sums in smem.
__global__ __launch_bounds__(256) void scanC(int n, int nb) {
    __shared__ int sb_[256];
    int t = threadIdx.x;
    int v = (t < nb) ? g_bsum[t] : 0;
    sb_[t] = v; __syncthreads();
    for (int off = 1; off < 256; off <<= 1) {
        int u = (t >= off) ? sb_[t - off] : 0;
        __syncthreads(); sb_[t] += u; __syncthreads();
    }
    if (t < nb) sb_[t] -= v;
    __syncthreads();
    int i = blockIdx.x * 256 + t;
    if (i >= n) return;
    int base = sb_[i >> 9] + g_prefix[i];
    g_rowstart[i] = base;
    g_cursor[i]   = base;
    g_dis[i]      = rsqrtf((float)g_deg[i] + 1.0f);
}

// CSR fill: packs (src, dis[src]) per edge; 4 edges per thread for MLP.
__global__ void fill_csr(const int* __restrict__ src, const int* __restrict__ dst, int E) {
    int base = (blockIdx.x * blockDim.x + threadIdx.x) * 4;
    if (base + 3 < E) {
        int4 d = *(const int4*)&dst[base];
        int4 s = *(const int4*)&src[base];
        float f0 = g_dis[s.x], f1 = g_dis[s.y], f2 = g_dis[s.z], f3 = g_dis[s.w];
        int p0 = atomicAdd(&g_cursor[d.x], 1);
        int p1 = atomicAdd(&g_cursor[d.y], 1);
        int p2 = atomicAdd(&g_cursor[d.z], 1);
        int p3 = atomicAdd(&g_cursor[d.w], 1);
        g_csr2[p0] = make_int2(s.x, __float_as_int(f0));
        g_csr2[p1] = make_int2(s.y, __float_as_int(f1));
        g_csr2[p2] = make_int2(s.z, __float_as_int(f2));
        g_csr2[p3] = make_int2(s.w, __float_as_int(f3));
    } else {
        for (int e = base; e < E; e++) {
            int s = src[e];
            int p = atomicAdd(&g_cursor[dst[e]], 1);
            g_csr2[p] = make_int2(s, __float_as_int(g_dis[s]));
        }
    }
}

// ---------------------------------------------------------------------------
// Layer-1 GEMM (fp32 A): cp.async raw double-buffer + image double-buffer so
// the fp32->bf16 hi/lo convert of chunk c+1 overlaps the HMMA drain of chunk c.
// h1[m][n] = half( sum_k x[m][k] * W1[k][n] )
__global__ __launch_bounds__(256) void gemm1(
    const float* __restrict__ A, const uint4* __restrict__ Bhi,
    const uint4* __restrict__ Blo, __half* __restrict__ Cout, int M)
{
    // MTILE=128, NDIM=128, KDIM=256, WM=4, WN=2, NCH=4
    constexpr int IMGA0 = 0;        // 2 bufs x (hi 16384 + lo 16384)
    constexpr int IMGB0 = 65536;    // 2 bufs x (hi 16384 + lo 16384)
    constexpr int RAW0  = 131072;   // 2 bufs x 32768
    constexpr int BNV   = 128 * 8;  // uint4 per B hi chunk

    extern __shared__ char smem[];
    const uint32_t sb = smem_u32(smem);
    const int tid  = threadIdx.x;
    const int wid  = tid >> 5, lane = tid & 31;
    const int wm   = wid >> 1, wn = wid & 1;
    const int m0   = blockIdx.x * 128;
    const int row_l  = lane & 15;
    const int colsel = (lane >> 4) * 8;

    float acc[2][16][4];
#pragma unroll
    for (int i = 0; i < 2; i++)
#pragma unroll
        for (int j = 0; j < 16; j++)
#pragma unroll
            for (int q = 0; q < 4; q++) acc[i][j][q] = 0.0f;

    auto copy_raw = [&](int c, int buf) {
        uint32_t raw = sb + RAW0 + buf * 32768;
        for (int g = tid; g < 128 * 16; g += 256) {
            int r  = g >> 4;
            int cb = (g & 15) * 16;
            int gm = m0 + r;
            const char* srcp = (const char*)&A[(size_t)(gm < M ? gm : 0) * 256 + c * 64] + cb;
            cp_async16(raw + r * 256 + cb, srcp, (gm < M) ? 16 : 0);
        }
        CP_COMMIT();
    };
    auto convert_chunk = [&](int rbuf, int ibuf) {
        const char* rawp = smem + RAW0 + rbuf * 32768;
        char* ih = smem + IMGA0 + ibuf * 32768;
        char* il = ih + 16384;
        for (int i = tid; i < 128 * 16; i += 256) {
            int m = i >> 4, kk = (i & 15) * 4;
            float4 v = *(const float4*)(rawp + m * 256 + (i & 15) * 16);
            __nv_bfloat16 h0 = __float2bfloat16_rn(v.x), h1 = __float2bfloat16_rn(v.y);
            __nv_bfloat16 h2 = __float2bfloat16_rn(v.z), h3 = __float2bfloat16_rn(v.w);
            __nv_bfloat16 l0 = __float2bfloat16_rn(v.x - __bfloat162float(h0));
            __nv_bfloat16 l1 = __float2bfloat16_rn(v.y - __bfloat162float(h1));
            __nv_bfloat16 l2 = __float2bfloat16_rn(v.z - __bfloat162float(h2));
            __nv_bfloat16 l3 = __float2bfloat16_rn(v.w - __bfloat162float(h3));
            int off = SW128(m * 128 + kk * 2);
            *(uint2*)(ih + off) = make_uint2(pack_bf2(h0, h1), pack_bf2(h2, h3));
            *(uint2*)(il + off) = make_uint2(pack_bf2(l0, l1), pack_bf2(l2, l3));
        }
    };
    auto stageB = [&](int c, int buf) {
        uint4* bh = (uint4*)(smem + IMGB0 + buf * 32768);
        uint4* bl = bh + 1024;
        const uint4* gh = Bhi + (size_t)c * BNV;
        const uint4* gl = Blo + (size_t)c * BNV;
        for (int i = tid; i < BNV; i += 256) { bh[i] = gh[i]; bl[i] = gl[i]; }
    };

    // preamble: raw0 -> img0 + B0; prefetch raw1
    copy_raw(0, 0);
    CP_WAIT0(); __syncthreads();
    copy_raw(1, 1);
    convert_chunk(0, 0);
    stageB(0, 0);
    __syncthreads();

    for (int c = 0; c < 4; c++) {
        const int buf = c & 1;
        const uint32_t ah_b = sb + IMGA0 + buf * 32768;
        const uint32_t al_b = ah_b + 16384;
        const uint32_t bh_b = sb + IMGB0 + buf * 32768;
        const uint32_t bl_b = bh_b + 16384;
#pragma unroll
        for (int k16 = 0; k16 < 4; k16++) {
            const int kb = k16 * 16;
            uint32_t ah[2][4], al[2][4];
#pragma unroll
            for (int im = 0; im < 2; im++) {
                int aoff = SW128((wm * 32 + im * 16 + row_l) * 128 + (kb + colsel) * 2);
                ldsm_x4(ah[im], ah_b + aoff);
                ldsm_x4(al[im], al_b + aoff);
            }
#pragma unroll
            for (int j2 = 0; j2 < 4; j2++) {
                int boff = SW128((wn * 64 + j2 * 16 + row_l) * 128 + (kb + colsel) * 2);
                uint32_t bh[4], bl[4];
                ldsm_x4(bh, bh_b + boff);
                ldsm_x4(bl, bl_b + boff);
#pragma unroll
                for (int im = 0; im < 2; im++) {
                    float* d0 = acc[im][2 * j2];
                    float* d1 = acc[im][2 * j2 + 1];
                    mma_bf16(d0, ah[im], bh[0], bh[2]);
                    mma_bf16(d0, ah[im], bl[0], bl[2]);
                    mma_bf16(d0, al[im], bh[0], bh[2]);
                    mma_bf16(d1, ah[im], bh[1], bh[3]);
                    mma_bf16(d1, ah[im], bl[1], bl[3]);
                    mma_bf16(d1, al[im], bh[1], bh[3]);
                }
            }
        }
        if (c + 1 < 4) {
            CP_WAIT0(); __syncthreads();               // raw(c+1) visible
            convert_chunk((c + 1) & 1, (c + 1) & 1);   // overlaps HMMA drain of chunk c
            stageB(c + 1, (c + 1) & 1);
            if (c + 2 < 4) copy_raw(c + 2, (c + 2) & 1);
            __syncthreads();
        }
    }

#pragma unroll
    for (int im = 0; im < 2; im++) {
        int row0 = m0 + wm * 32 + im * 16 + (lane >> 2);
        int row1 = row0 + 8;
#pragma unroll
        for (int j = 0; j < 8; j++) {
            int col = wn * 64 + j * 8 + (lane & 3) * 2;
            if (row0 < M)
                *(__half2*)&Cout[(size_t)row0 * C1 + col] =
                    __floats2half2_rn(acc[im][j][0], acc[im][j][1]);
            if (row1 < M)
                *(__half2*)&Cout[(size_t)row1 * C1 + col] =
                    __floats2half2_rn(acc[im][j][2], acc[im][j][3]);
        }
    }
}

// ---------------------------------------------------------------------------
// Layer-2 GEMM: A = pre-swizzled x2 hi/lo planes (written by agg128).
// NO convert; cp.async straight into double-buffered A-image slots.
__global__ __launch_bounds__(256) void gemm2_pre(
    const unsigned char* __restrict__ Ahi, const unsigned char* __restrict__ Alo,
    const uint4* __restrict__ Bhi, const uint4* __restrict__ Blo,
    __half* __restrict__ Cout, int M)
{
    // MTILE=256, NDIM=64, KDIM=128, WM=8, WN=1, NCH=2
    constexpr int IMGA0 = 0;        // 2 bufs x (hi 32768 + lo 32768)
    constexpr int IMGB0 = 131072;   // 2 chunks x (hi 8192 + lo 8192)
    constexpr int BNV   = 64 * 8;

    extern __shared__ char smem[];
    const uint32_t sb = smem_u32(smem);
    const int tid  = threadIdx.x;
    const int wid  = tid >> 5, lane = tid & 31;
    const int wm   = wid;
    const int m0   = blockIdx.x * 256;
    const int row_l  = lane & 15;
    const int colsel = (lane >> 4) * 8;

    float acc[2][8][4];
#pragma unroll
    for (int i = 0; i < 2; i++)
#pragma unroll
        for (int j = 0; j < 8; j++)
#pragma unroll
            for (int q = 0; q < 4; q++) acc[i][j][q] = 0.0f;

    auto copyA = [&](int c) {
        uint32_t ih = sb + IMGA0 + c * 65536;
        uint32_t il = ih + 32768;
        for (int g = tid; g < 256 * 8; g += 256) {
            int r  = g >> 3;
            int cb = (g & 7) * 16;
            int gm = m0 + r;
            size_t base = ((size_t)c * NN_MAX + (gm < M ? gm : 0)) * 128 + cb;
            int sz = (gm < M) ? 16 : 0;
            cp_async16(ih + r * 128 + cb, Ahi + base, sz);
            cp_async16(il + r * 128 + cb, Alo + base, sz);
        }
        CP_COMMIT();
    };

    copyA(0);
    copyA(1);
    // stage both B chunks (LDG->STS, L2-hot)
    for (int c = 0; c < 2; c++) {
        uint4* bh = (uint4*)(smem + IMGB0 + c * 16384);
        uint4* bl = bh + 512;
        const uint4* gh = Bhi + (size_t)c * BNV;
        const uint4* gl = Blo + (size_t)c * BNV;
        for (int i = tid; i < BNV; i += 256) { bh[i] = gh[i]; bl[i] = gl[i]; }
    }

    for (int c = 0; c < 2; c++) {
        if (c == 0) CP_WAIT1(); else CP_WAIT0();
        __syncthreads();
        const uint32_t ah_b = sb + IMGA0 + c * 65536;
        const uint32_t al_b = ah_b + 32768;
        const uint32_t bh_b = sb + IMGB0 + c * 16384;
        const uint32_t bl_b = bh_b + 8192;
#pragma unroll
        for (int k16 = 0; k16 < 4; k16++) {
            const int kb = k16 * 16;
            uint32_t ah[2][4], al[2][4];
#pragma unroll
            for (int im = 0; im < 2; im++) {
                int aoff = SW128((wm * 32 + im * 16 + row_l) * 128 + (kb + colsel) * 2);
                ldsm_x4(ah[im], ah_b + aoff);
                ldsm_x4(al[im], al_b + aoff);
            }
#pragma unroll
            for (int j2 = 0; j2 < 4; j2++) {
                int boff = SW128((j2 * 16 + row_l) * 128 + (kb + colsel) * 2);
                uint32_t bh[4], bl[4];
                ldsm_x4(bh, bh_b + boff);
                ldsm_x4(bl, bl_b + boff);
#pragma unroll
                for (int im = 0; im < 2; im++) {
                    float* d0 = acc[im][2 * j2];
                    float* d1 = acc[im][2 * j2 + 1];
                    mma_bf16(d0, ah[im], bh[0], bh[2]);
                    mma_bf16(d0, ah[im], bl[0], bl[2]);
                    mma_bf16(d0, al[im], bh[0], bh[2]);
                    mma_bf16(d1, ah[im], bh[1], bh[3]);
                    mma_bf16(d1, ah[im], bl[1], bl[3]);
                    mma_bf16(d1, al[im], bh[1], bh[3]);
                }
            }
        }
    }

#pragma unroll
    for (int im = 0; im < 2; im++) {
        int row0 = m0 + wm * 32 + im * 16 + (lane >> 2);
        int row1 = row0 + 8;
#pragma unroll
        for (int j = 0; j < 8; j++) {
            int col = j * 8 + (lane & 3) * 2;
            if (row0 < M)
                *(__half2*)&Cout[(size_t)row0 * C2 + col] =
                    __floats2half2_rn(acc[im][j][0], acc[im][j][1]);
            if (row1 < M)
                *(__half2*)&Cout[(size_t)row1 * C2 + col] =
                    __floats2half2_rn(acc[im][j][2], acc[im][j][3]);
        }
    }
}

// ---------------------------------------------------------------------------
// Gather-reduce aggregation, 128 fp16 channels: one warp per dst node.
// Epilogue writes relu result as pre-swizzled bf16 hi/lo planes for gemm2.
__global__ __launch_bounds__(256)
void agg128(const __half* __restrict__ hs, const float* __restrict__ bias, int n) {
    int warp = (blockIdx.x * blockDim.x + threadIdx.x) >> 5;
    int lane = threadIdx.x & 31;
    if (warp >= n) return;
    const int node = warp;
    const float dnode = g_dis[node];

    float4 acc;
    {
        uint2 r = *(const uint2*)&hs[(size_t)node * C1 + lane * 4];
        float2 f0 = __half22float2(*(__half2*)&r.x);
        float2 f1 = __half22float2(*(__half2*)&r.y);
        acc = make_float4(f0.x * dnode, f0.y * dnode, f1.x * dnode, f1.y * dnode);
    }
    int e   = g_rowstart[node];
    int cnt = g_deg[node];

    while (cnt > 0) {
        int take = min(cnt, 32);
        int2 sd = make_int2(0, 0);
        if (lane < take) sd = g_csr2[e + lane];
        int k = 0;
        for (; k + 8 <= take; k += 8) {
            uint2 r[8]; float dq[8];
#pragma unroll
            for (int q = 0; q < 8; q++) {
                int sq = __shfl_sync(0xffffffffu, sd.x, k + q);
                dq[q]  = __int_as_float(__shfl_sync(0xffffffffu, sd.y, k + q));
                r[q] = *(const uint2*)&hs[(size_t)sq * C1 + lane * 4];
            }
#pragma unroll
            for (int q = 0; q < 8; q++) {
                float2 f0 = __half22float2(*(__half2*)&r[q].x);
                float2 f1 = __half22float2(*(__half2*)&r[q].y);
                acc.x = fmaf(f0.x, dq[q], acc.x);
                acc.y = fmaf(f0.y, dq[q], acc.y);
                acc.z = fmaf(f1.x, dq[q], acc.z);
                acc.w = fmaf(f1.y, dq[q], acc.w);
            }
        }
        for (; k < take; k++) {
            int sk = __shfl_sync(0xffffffffu, sd.x, k);
            float dk = __int_as_float(__shfl_sync(0xffffffffu, sd.y, k));
            uint2 r = *(const uint2*)&hs[(size_t)sk * C1 + lane * 4];
            float2 f0 = __half22float2(*(__half2*)&r.x);
            float2 f1 = __half22float2(*(__half2*)&r.y);
            acc.x = fmaf(f0.x, dk, acc.x);
            acc.y = fmaf(f0.y, dk, acc.y);
            acc.z = fmaf(f1.x, dk, acc.z);
            acc.w = fmaf(f1.y, dk, acc.w);
        }
        e += take; cnt -= take;
    }

    float4 bb = ((const float4*)bias)[lane];
    float rx = fmaxf(fmaf(dnode, acc.x, bb.x), 0.0f);
    float ry = fmaxf(fmaf(dnode, acc.y, bb.y), 0.0f);
    float rz = fmaxf(fmaf(dnode, acc.z, bb.z), 0.0f);
    float rw = fmaxf(fmaf(dnode, acc.w, bb.w), 0.0f);

    // split to bf16 hi/lo, write pre-swizzled planes
    __nv_bfloat16 h0 = __float2bfloat16_rn(rx), h1 = __float2bfloat16_rn(ry);
    __nv_bfloat16 h2 = __float2bfloat16_rn(rz), h3 = __float2bfloat16_rn(rw);
    __nv_bfloat16 l0 = __float2bfloat16_rn(rx - __bfloat162float(h0));
    __nv_bfloat16 l1 = __float2bfloat16_rn(ry - __bfloat162float(h1));
    __nv_bfloat16 l2 = __float2bfloat16_rn(rz - __bfloat162float(h2));
    __nv_bfloat16 l3 = __float2bfloat16_rn(rw - __bfloat162float(h3));
    int chunk = lane >> 4;
    int inner = ((lane & 15) * 8) ^ ((node & 7) << 4);
    size_t base = ((size_t)chunk * NN_MAX + node) * 128 + inner;
    *(uint2*)(g_x2hi + base) = make_uint2(pack_bf2(h0, h1), pack_bf2(h2, h3));
    *(uint2*)(g_x2lo + base) = make_uint2(pack_bf2(l0, l1), pack_bf2(l2, l3));
}

// 64-ch fp16 aggregation: one warp per node, each lane owns 2 channels (half2).
__global__ __launch_bounds__(256)
void agg64(const __half* __restrict__ hs, const float* __restrict__ bias,
           float* __restrict__ out, int n) {
    int warp = (blockIdx.x * blockDim.x + threadIdx.x) >> 5;
    int lane = threadIdx.x & 31;
    if (warp >= n) return;
    const int node = warp;
    const float dnode = g_dis[node];

    float2 acc;
    {
        uint32_t r = *(const uint32_t*)&hs[(size_t)node * C2 + lane * 2];
        float2 f = __half22float2(*(__half2*)&r);
        acc = make_float2(f.x * dnode, f.y * dnode);
    }
    int e   = g_rowstart[node];
    int cnt = g_deg[node];

    while (cnt > 0) {
        int take = min(cnt, 32);
        int2 sd = make_int2(0, 0);
        if (lane < take) sd = g_csr2[e + lane];
        int k = 0;
        for (; k + 8 <= take; k += 8) {
            uint32_t r[8]; float dq[8];
#pragma unroll
            for (int q = 0; q < 8; q++) {
                int sq = __shfl_sync(0xffffffffu, sd.x, k + q);
                dq[q]  = __int_as_float(__shfl_sync(0xffffffffu, sd.y, k + q));
                r[q] = *(const uint32_t*)&hs[(size_t)sq * C2 + lane * 2];
            }
#pragma unroll
            for (int q = 0; q < 8; q++) {
                float2 f = __half22float2(*(__half2*)&r[q]);
                acc.x = fmaf(f.x, dq[q], acc.x);
                acc.y = fmaf(f.y, dq[q], acc.y);
            }
        }
        for (; k < take; k++) {
            int sk = __shfl_sync(0xffffffffu, sd.x, k);
            float dk = __int_as_float(__shfl_sync(0xffffffffu, sd.y, k));
            uint32_t r = *(const uint32_t*)&hs[(size_t)sk * C2 + lane * 2];
            float2 f = __half22float2(*(__half2*)&r);
            acc.x = fmaf(f.x, dk, acc.x);
            acc.y = fmaf(f.y, dk, acc.y);
        }
        e += take; cnt -= take;
    }

    float2 bb = ((const float2*)bias)[lane];
    float2 r;
    r.x = fmaxf(fmaf(dnode, acc.x, bb.x), 0.0f);
    r.y = fmaxf(fmaf(dnode, acc.y, bb.y), 0.0f);
    *(float2*)&out[(size_t)node * C2 + lane * 2] = r;
}

// ---------------------------------------------------------------------------
extern "C" void kernel_launch(void* const* d_in, const int* in_sizes, int n_in,
                              void* d_out, int out_size) {
    const float* x  = (const float*)d_in[0];
    const int*   ei = (const int*)d_in[1];
    const float* W1 = (const float*)d_in[2];
    const float* b1 = (const float*)d_in[3];
    const float* W2 = (const float*)d_in[4];
    const float* b2 = (const float*)d_in[5];
    float* out = (float*)d_out;

    const int E = in_sizes[1] / 2;
    const int N = in_sizes[0] / IN_CH;
    const int* src = ei;
    const int* dst = ei + E;

    __half *h1, *h2;
    unsigned char *x2h, *x2l;
    uint4 *w1h, *w1l, *w2h, *w2l;
    cudaGetSymbolAddress((void**)&h1,  g_h1);
    cudaGetSymbolAddress((void**)&h2,  g_h2);
    cudaGetSymbolAddress((void**)&x2h, g_x2hi);
    cudaGetSymbolAddress((void**)&x2l, g_x2lo);
    cudaGetSymbolAddress((void**)&w1h, g_W1hi);
    cudaGetSymbolAddress((void**)&w1l, g_W1lo);
    cudaGetSymbolAddress((void**)&w2h, g_W2hi);
    cudaGetSymbolAddress((void**)&w2l, g_W2lo);

    constexpr int SMEM1 = 65536 + 65536 + 65536;   // imgA + imgB + raw = 196608
    constexpr int SMEM2 = 131072 + 32768;          // imgA bufs + B = 163840
    cudaFuncSetAttribute(gemm1,     cudaFuncAttributeMaxDynamicSharedMemorySize, SMEM1);
    cudaFuncSetAttribute(gemm2_pre, cudaFuncAttributeMaxDynamicSharedMemorySize, SMEM2);

    // Lazily-created side stream + fork/join events (first call is uncaptured).
    static cudaStream_t s_side = nullptr;
    static cudaEvent_t  ev_fork = nullptr, ev_chain = nullptr;
    if (!s_side) {
        cudaStreamCreateWithFlags(&s_side, cudaStreamNonBlocking);
        cudaEventCreateWithFlags(&ev_fork,  cudaEventDisableTiming);
        cudaEventCreateWithFlags(&ev_chain, cudaEventDisableTiming);
    }

    // prep: zero deg + weight images (R9-proven: fused, pre-fork, main stream)
    {
        int total = (N > IN_CH * C1) ? N : IN_CH * C1;
        prep_kernel<<<(total + 255) / 256, 256>>>(W1, W2, N);
    }

    // Fork: CSR-build chain on side stream, gemm1 on main stream (independent).
    cudaEventRecord(ev_fork, 0);
    cudaStreamWaitEvent(s_side, ev_fork, 0);

    deg_kernel<<<((E + 3) / 4 + 255) / 256, 256, 0, s_side>>>(dst, E);
    int nb = (N + 511) / 512;
    scanA<<<nb, 512, 0, s_side>>>(N);
    scanC<<<(N + 255) / 256, 256, 0, s_side>>>(N, nb);
    fill_csr<<<((E + 3) / 4 + 255) / 256, 256, 0, s_side>>>(src, dst, E);
    cudaEventRecord(ev_chain, s_side);

    // ---- layer 1 GEMM (no dis dependency) ----
    gemm1<<<(N + 127) / 128, 256, SMEM1>>>(x, w1h, w1l, h1, N);

    // Join: aggregation needs both gemm1 (stream order) and the CSR chain.
    cudaStreamWaitEvent(0, ev_chain, 0);
    agg128<<<(N * 32 + 255) / 256, 256>>>(h1, b1, N);

    // ---- layer 2 (serial on main — proven fastest topology) ----
    gemm2_pre<<<(N + 255) / 256, 256, SMEM2>>>(x2h, x2l, w2h, w2l, h2, N);
    agg64<<<(N * 32 + 255) / 256, 256>>>(h2, b2, out, N);
}